// round 2
// baseline (speedup 1.0000x reference)
#include <cuda_runtime.h>

// Problem constants
#define NPOS 2048   // B*S = 4*512
#define DM   512    // d_model
#define NH   8      // heads
#define DH   64     // head dim
#define TT   32     // tgt positions per (b,s)

// Scratch (device globals: allocation-free per harness rules)
__device__ float g_Q  [NPOS * DM];            //  4 MB   q projection
__device__ float g_P  [NPOS * NH * DM];       // 33.5 MB p[i,h,:] = W_k_h^T q_h
__device__ float g_U  [NPOS * NH * DM];       // 33.5 MB u[i,h,:] = sum_t a * tgt
__device__ float g_CTX[NPOS * DM];            //  4 MB   attention output
__device__ int   g_AM [NPOS];                 // all-masked flags
__device__ int   g_MaskMode;                  // 0=u8, 1=i32, 2=f32

// ---------------------------------------------------------------------------
// Mask dtype detection: the harness only guarantees f32/i32/bf16 delivery, so
// the bool tgt_padding_mask may arrive as u8, i32, or f32. Scan the first
// 16384 u32 words (safe under the smallest possible layout, 65536 u8 bytes):
//   word == 0x3F800000            -> float32 (1.0f)
//   else word > 1                 -> u8/bool (a set byte at offset%4!=0)
//   else all words in {0,1}       -> int32
// With ~10% mask density these rules identify the layout with certainty.
// ---------------------------------------------------------------------------
__global__ void detect_mask_kernel(const unsigned* __restrict__ w, int nwords,
                                   int* __restrict__ mode) {
    __shared__ int flags[2];
    if (threadIdx.x < 2) flags[threadIdx.x] = 0;
    __syncthreads();
    for (int j = threadIdx.x; j < nwords; j += blockDim.x) {
        unsigned v = w[j];
        if (v == 0x3F800000u)      atomicOr(&flags[0], 1);
        else if (v > 1u)           atomicOr(&flags[1], 1);
    }
    __syncthreads();
    if (threadIdx.x == 0)
        *mode = flags[0] ? 2 : (flags[1] ? 0 : 1);
}

// ---------------------------------------------------------------------------
// Tiled GEMM: C[M,N] = A[M,K] @ op(B) + bias, 64x64 tile, BK=16, 256 threads,
// 4x4 per-thread microtile. BNT=true: B is (N,K) row-major (i.e. X @ W^T).
// BNT=false: B is (K,N) row-major. blockIdx.z selects a per-head slice via
// the *oz strides. ZMASK: zero rows flagged in rmask (all-masked positions).
// ---------------------------------------------------------------------------
template <bool BNT, bool ZMASK>
__global__ __launch_bounds__(256) void gemm64k(
    const float* __restrict__ A, int lda, int aoz,
    const float* __restrict__ B, int ldb, int boz,
    float* __restrict__ C, int ldc, int coz,
    const float* __restrict__ bias, int bioz,
    int K, const int* __restrict__ rmask)
{
    __shared__ float As[16][64];   // As[k][m]
    __shared__ float Bs[16][64];   // Bs[k][n]

    const int z = blockIdx.z;
    A += (size_t)z * aoz;
    B += (size_t)z * boz;
    C += (size_t)z * coz;
    if (bias) bias += (size_t)z * bioz;

    const int m0 = blockIdx.x * 64, n0 = blockIdx.y * 64;
    const int tid = threadIdx.x;
    const int tx = tid & 15, ty = tid >> 4;
    const int arow = tid >> 2, acol = (tid & 3) * 4;

    float acc[4][4] = {};

    for (int kt = 0; kt < K; kt += 16) {
        float4 av = *(const float4*)&A[(size_t)(m0 + arow) * lda + kt + acol];
        As[acol + 0][arow] = av.x; As[acol + 1][arow] = av.y;
        As[acol + 2][arow] = av.z; As[acol + 3][arow] = av.w;
        if (BNT) {
            float4 bv = *(const float4*)&B[(size_t)(n0 + arow) * ldb + kt + acol];
            Bs[acol + 0][arow] = bv.x; Bs[acol + 1][arow] = bv.y;
            Bs[acol + 2][arow] = bv.z; Bs[acol + 3][arow] = bv.w;
        } else {
            float4 bv = *(const float4*)&B[(size_t)(kt + ty) * ldb + n0 + tx * 4];
            *(float4*)&Bs[ty][tx * 4] = bv;
        }
        __syncthreads();

        #pragma unroll
        for (int kk = 0; kk < 16; kk++) {
            float4 a4 = *(const float4*)&As[kk][ty * 4];
            float4 b4 = *(const float4*)&Bs[kk][tx * 4];
            float ar[4] = {a4.x, a4.y, a4.z, a4.w};
            float br[4] = {b4.x, b4.y, b4.z, b4.w};
            #pragma unroll
            for (int i = 0; i < 4; i++)
                #pragma unroll
                for (int j = 0; j < 4; j++)
                    acc[i][j] += ar[i] * br[j];
        }
        __syncthreads();
    }

    #pragma unroll
    for (int i = 0; i < 4; i++) {
        const int r = m0 + ty * 4 + i;
        const bool zr = ZMASK ? (rmask[r] != 0) : false;
        #pragma unroll
        for (int j = 0; j < 4; j++) {
            const int cn = n0 + tx * 4 + j;
            float v = acc[i][j];
            if (bias) v += bias[cn];
            if (zr) v = 0.f;
            C[(size_t)r * ldc + cn] = v;
        }
    }
}

// ---------------------------------------------------------------------------
// Fused attention core: one block per (b,s) position.
// Holds the 32x512 tgt tile + p[8,512] in smem; computes logits (+k-bias dot),
// masked softmax (all-masked -> unmasked softmax, zeroed later in out-proj),
// and u[h,:] = sum_t a[h,t] * tgt[t,:].
// ---------------------------------------------------------------------------
__global__ __launch_bounds__(256) void attn_core(
    const float* __restrict__ tgt,
    const float* __restrict__ Q,
    const float* __restrict__ P,
    const void* __restrict__ mask_raw,
    const int* __restrict__ mask_mode,
    const float* __restrict__ ipb,
    float* __restrict__ U,
    int* __restrict__ allm)
{
    extern __shared__ float sm[];
    float* s_tile = sm;              // 32*512 = 16384
    float* s_p    = sm + 16384;      //  8*512 =  4096
    float* s_a    = sm + 20480;      //  8*32  =   256 (logits, then softmax a)
    float* s_c    = sm + 20736;      //  8     (q . b_k per head)
    float* s_m    = sm + 20744;      // 32     (mask flags)
    float* s_am   = sm + 20776;      //  1     (all-masked flag)

    const int i   = blockIdx.x;
    const int tid = threadIdx.x;
    const int lane = tid & 31, w = tid >> 5;   // 8 warps

    // Load tgt tile (64KB) and p row (16KB), float4, front-batched
    const float4* tg  = (const float4*)(tgt + (size_t)i * (TT * DM));
    float4* st4 = (float4*)s_tile;
    #pragma unroll
    for (int r = 0; r < 16; r++) st4[tid + 256 * r] = tg[tid + 256 * r];

    const float4* pg  = (const float4*)(P + (size_t)i * (NH * DM));
    float4* sp4 = (float4*)s_p;
    #pragma unroll
    for (int r = 0; r < 4; r++) sp4[tid + 256 * r] = pg[tid + 256 * r];

    // c[h] = q_h . b_k_h  (logit bias term; exact fold of the k-bias)
    {
        const float* qr = Q   + (size_t)i * DM + w * DH;
        const float* br = ipb + DM + w * DH;
        float cs = qr[lane] * br[lane] + qr[lane + 32] * br[lane + 32];
        #pragma unroll
        for (int off = 16; off; off >>= 1)
            cs += __shfl_down_sync(0xffffffffu, cs, off);
        if (lane == 0) s_c[w] = cs;
    }
    // mask + all-masked flag (warp 0), dtype-adaptive read
    if (w == 0) {
        const int mode = *mask_mode;
        unsigned mv;
        if (mode == 0)      mv = ((const unsigned char*)mask_raw)[(size_t)i * TT + lane];
        else if (mode == 1) mv = ((const unsigned*)mask_raw)[(size_t)i * TT + lane] != 0u;
        else                mv = ((const float*)mask_raw)[(size_t)i * TT + lane] != 0.f;
        s_m[lane] = mv ? 1.f : 0.f;
        unsigned bal = __ballot_sync(0xffffffffu, mv != 0);
        if (lane == 0) {
            int am = (bal == 0xffffffffu) ? 1 : 0;
            s_am[0] = (float)am;
            allm[i] = am;
        }
    }
    __syncthreads();

    // logits[h,t] = p_h . tgt_t + c[h]; lanes split K (conflict-free float4)
    for (int idx = w; idx < NH * TT; idx += 8) {
        const int h = idx >> 5, t = idx & 31;
        const float4* pr = (const float4*)(s_p + h * DM);
        const float4* tr = (const float4*)(s_tile + t * DM);
        float sum = 0.f;
        #pragma unroll
        for (int kk = lane; kk < 128; kk += 32) {
            float4 a4 = pr[kk], b4 = tr[kk];
            sum += a4.x * b4.x + a4.y * b4.y + a4.z * b4.z + a4.w * b4.w;
        }
        #pragma unroll
        for (int off = 16; off; off >>= 1)
            sum += __shfl_down_sync(0xffffffffu, sum, off);
        if (lane == 0) s_a[idx] = sum + s_c[h];
    }
    __syncthreads();

    // softmax over t (one warp per head); scale 1/sqrt(64) = 0.125
    {
        const float am = s_am[0];
        float l = s_a[w * 32 + lane];
        const bool inv = (s_m[lane] != 0.f) && (am == 0.f);
        l = inv ? -1e30f : l * 0.125f;
        float m = l;
        #pragma unroll
        for (int off = 16; off; off >>= 1)
            m = fmaxf(m, __shfl_xor_sync(0xffffffffu, m, off));
        float e = inv ? 0.f : __expf(l - m);
        float s = e;
        #pragma unroll
        for (int off = 16; off; off >>= 1)
            s += __shfl_xor_sync(0xffffffffu, s, off);
        s_a[w * 32 + lane] = e / s;
    }
    __syncthreads();

    // u[h,:] = sum_t a[h,t] * tgt[t,:]  (float4 over K, conflict-free)
    float4* u4 = (float4*)(U + (size_t)i * (NH * DM));
    const float4* tile4 = (const float4*)s_tile;
    #pragma unroll
    for (int r = 0; r < 4; r++) {
        const int o = tid + 256 * r;
        const int h = o >> 7, k4 = o & 127;
        const float* av = s_a + h * 32;
        float4 acc = make_float4(0.f, 0.f, 0.f, 0.f);
        #pragma unroll 8
        for (int t = 0; t < TT; t++) {
            const float a = av[t];
            const float4 tv = tile4[t * 128 + k4];
            acc.x += a * tv.x; acc.y += a * tv.y;
            acc.z += a * tv.z; acc.w += a * tv.w;
        }
        u4[o] = acc;
    }
}

extern "C" void kernel_launch(void* const* d_in, const int* in_sizes, int n_in,
                              void* d_out, int out_size) {
    const float*         src  = (const float*)d_in[0];
    const float*         tgt  = (const float*)d_in[1];
    const void*          mask = d_in[2];                         // dtype detected
    const float*         ipw  = (const float*)d_in[3];          // (1536,512)
    const float*         ipb  = (const float*)d_in[4];          // (1536,)
    const float*         opw  = (const float*)d_in[5];          // (512,512)
    const float*         opb  = (const float*)d_in[6];          // (512,)
    float*               out  = (float*)d_out;

    float *Q, *P, *U, *CTX; int *AM, *MODE;
    cudaGetSymbolAddress((void**)&Q,    g_Q);
    cudaGetSymbolAddress((void**)&P,    g_P);
    cudaGetSymbolAddress((void**)&U,    g_U);
    cudaGetSymbolAddress((void**)&CTX,  g_CTX);
    cudaGetSymbolAddress((void**)&AM,   g_AM);
    cudaGetSymbolAddress((void**)&MODE, g_MaskMode);

    // 0) detect mask dtype (u8 / i32 / f32); 16384 words safe for all layouts
    detect_mask_kernel<<<1, 256>>>((const unsigned*)mask, 16384, MODE);

    // 1) Q = src @ Wq^T + bq                       (2048,512)x(512,512)
    gemm64k<true, false><<<dim3(32, 8, 1), 256>>>(
        src, 512, 0, ipw, 512, 0, Q, 512, 0, ipb, 0, 512, nullptr);

    // 2) P[:,h,:] = Q[:,h*64:+64] @ Wk_h           per-head (2048,64)x(64,512)
    gemm64k<false, false><<<dim3(32, 8, 8), 256>>>(
        Q, 512, 64, ipw + 512 * 512, 512, 64 * 512,
        P, 4096, 512, nullptr, 0, 64, nullptr);

    // 3) fused attention: logits -> softmax -> U
    const int smem = 20784 * 4;  // ~83 KB dynamic
    cudaFuncSetAttribute(attn_core, cudaFuncAttributeMaxDynamicSharedMemorySize, smem);
    attn_core<<<2048, 256, smem>>>(tgt, Q, P, mask, MODE, ipb, U, AM);

    // 4) ctx[:,h*64:+64] = U[:,h,:] @ Wv_h^T + bv  per-head (2048,512)x(512,64)
    gemm64k<true, false><<<dim3(32, 1, 8), 256>>>(
        U, 4096, 512, ipw + 1024 * 512, 512, 64 * 512,
        CTX, 512, 64, ipb + 1024, 64, 512, nullptr);

    // 5) out = ctx @ Wo^T + bo, zeroed where all tgt positions were masked
    gemm64k<true, true><<<dim3(32, 8, 1), 256>>>(
        CTX, 512, 0, opw, 512, 0, out, 512, 0, opb, 0, 512, AM);
}

// round 3
// speedup vs baseline: 1.4713x; 1.4713x over previous
#include <cuda_runtime.h>

// Problem constants
#define NPOS 2048   // B*S = 4*512
#define DM   512    // d_model
#define NH   8      // heads
#define DH   64     // head dim
#define TT   32     // tgt positions per (b,s)

// Scratch (device globals: allocation-free per harness rules)
__device__ float g_Q  [NPOS * DM];            //  4 MB   q projection
__device__ float g_P  [NPOS * NH * DM];       // 33.5 MB p[i,h,:] = W_k_h^T q_h
__device__ float g_U  [NPOS * NH * DM];       // 33.5 MB u[i,h,:] = sum_t a * tgt
__device__ float g_CTX[NPOS * DM];            //  4 MB   attention output
__device__ int   g_AM [NPOS];                 // all-masked flags
__device__ int   g_MaskMode;                  // 0=u8, 1=i32, 2=f32

// ---------------------------------------------------------------------------
// Mask dtype detection (bool may arrive as u8, i32 or f32). See R1 notes.
// ---------------------------------------------------------------------------
__global__ void detect_mask_kernel(const unsigned* __restrict__ w, int nwords,
                                   int* __restrict__ mode) {
    __shared__ int flags[2];
    if (threadIdx.x < 2) flags[threadIdx.x] = 0;
    __syncthreads();
    for (int j = threadIdx.x; j < nwords; j += blockDim.x) {
        unsigned v = w[j];
        if (v == 0x3F800000u)      atomicOr(&flags[0], 1);
        else if (v > 1u)           atomicOr(&flags[1], 1);
    }
    __syncthreads();
    if (threadIdx.x == 0)
        *mode = flags[0] ? 2 : (flags[1] ? 0 : 1);
}

// ---------------------------------------------------------------------------
// GEMM: 128(M) x 64(N) tile, BK=16, 128 threads, 8x8 microtile (split frags
// at tx*4 / 32+tx*4 and ty*4 / 64+ty*4 for conflict-free LDS.128).
// C = A @ op(B) + bias. BNT=true: B is (N,K) row-major; else (K,N).
// blockIdx.z slices per-head via *oz strides. ZMASK zeroes flagged rows.
// ---------------------------------------------------------------------------
template <bool BNT, bool ZMASK>
__global__ __launch_bounds__(128) void gemm128(
    const float* __restrict__ A, int lda, int aoz,
    const float* __restrict__ B, int ldb, int boz,
    float* __restrict__ C, int ldc, int coz,
    const float* __restrict__ bias, int bioz,
    int K, const int* __restrict__ rmask)
{
    __shared__ float As[16][132];   // [k][m], padded
    __shared__ float Bs[16][68];    // [k][n], padded

    const int z = blockIdx.z;
    A += (size_t)z * aoz;
    B += (size_t)z * boz;
    C += (size_t)z * coz;
    if (bias) bias += (size_t)z * bioz;

    const int m0 = blockIdx.x * 128, n0 = blockIdx.y * 64;
    const int tid = threadIdx.x;
    const int tx = tid & 7, ty = tid >> 3;   // 8 x 16 thread grid

    float4 pa[4], pb[2];
    float acc[8][8] = {};

    // prologue loads (kt = 0)
    #pragma unroll
    for (int r = 0; r < 4; r++) {
        int a = tid + 128 * r;
        pa[r] = *(const float4*)&A[(size_t)(m0 + (a >> 2)) * lda + ((a & 3) << 2)];
    }
    #pragma unroll
    for (int r = 0; r < 2; r++) {
        int b = tid + 128 * r;
        if (BNT) pb[r] = *(const float4*)&B[(size_t)(n0 + (b >> 2)) * ldb + ((b & 3) << 2)];
        else     pb[r] = *(const float4*)&B[(size_t)(b >> 4) * ldb + n0 + ((b & 15) << 2)];
    }

    for (int kt = 0; kt < K; kt += 16) {
        // stage to smem
        #pragma unroll
        for (int r = 0; r < 4; r++) {
            int a = tid + 128 * r;
            int row = a >> 2, c4 = (a & 3) << 2;
            As[c4 + 0][row] = pa[r].x; As[c4 + 1][row] = pa[r].y;
            As[c4 + 2][row] = pa[r].z; As[c4 + 3][row] = pa[r].w;
        }
        #pragma unroll
        for (int r = 0; r < 2; r++) {
            int b = tid + 128 * r;
            if (BNT) {
                int n = b >> 2, c4 = (b & 3) << 2;
                Bs[c4 + 0][n] = pb[r].x; Bs[c4 + 1][n] = pb[r].y;
                Bs[c4 + 2][n] = pb[r].z; Bs[c4 + 3][n] = pb[r].w;
            } else {
                *(float4*)&Bs[b >> 4][(b & 15) << 2] = pb[r];
            }
        }
        __syncthreads();

        // prefetch next kt while computing
        if (kt + 16 < K) {
            #pragma unroll
            for (int r = 0; r < 4; r++) {
                int a = tid + 128 * r;
                pa[r] = *(const float4*)&A[(size_t)(m0 + (a >> 2)) * lda + kt + 16 + ((a & 3) << 2)];
            }
            #pragma unroll
            for (int r = 0; r < 2; r++) {
                int b = tid + 128 * r;
                if (BNT) pb[r] = *(const float4*)&B[(size_t)(n0 + (b >> 2)) * ldb + kt + 16 + ((b & 3) << 2)];
                else     pb[r] = *(const float4*)&B[(size_t)(kt + 16 + (b >> 4)) * ldb + n0 + ((b & 15) << 2)];
            }
        }

        #pragma unroll
        for (int kk = 0; kk < 16; kk++) {
            float4 a0 = *(const float4*)&As[kk][ty * 4];
            float4 a1 = *(const float4*)&As[kk][64 + ty * 4];
            float4 b0 = *(const float4*)&Bs[kk][tx * 4];
            float4 b1 = *(const float4*)&Bs[kk][32 + tx * 4];
            float am[8] = {a0.x, a0.y, a0.z, a0.w, a1.x, a1.y, a1.z, a1.w};
            float bn[8] = {b0.x, b0.y, b0.z, b0.w, b1.x, b1.y, b1.z, b1.w};
            #pragma unroll
            for (int i = 0; i < 8; i++)
                #pragma unroll
                for (int j = 0; j < 8; j++)
                    acc[i][j] += am[i] * bn[j];
        }
        __syncthreads();
    }

    // epilogue
    float4 bv0 = make_float4(0.f, 0.f, 0.f, 0.f), bv1 = bv0;
    if (bias) {
        bv0 = *(const float4*)&bias[n0 + tx * 4];
        bv1 = *(const float4*)&bias[n0 + 32 + tx * 4];
    }
    #pragma unroll
    for (int i = 0; i < 8; i++) {
        const int r = m0 + ((i < 4) ? (ty * 4 + i) : (64 + ty * 4 + i - 4));
        const bool zr = ZMASK ? (rmask[r] != 0) : false;
        float4 v0 = make_float4(acc[i][0] + bv0.x, acc[i][1] + bv0.y,
                                acc[i][2] + bv0.z, acc[i][3] + bv0.w);
        float4 v1 = make_float4(acc[i][4] + bv1.x, acc[i][5] + bv1.y,
                                acc[i][6] + bv1.z, acc[i][7] + bv1.w);
        if (zr) { v0 = make_float4(0.f, 0.f, 0.f, 0.f); v1 = v0; }
        *(float4*)&C[(size_t)r * ldc + n0 + tx * 4]      = v0;
        *(float4*)&C[(size_t)r * ldc + n0 + 32 + tx * 4] = v1;
    }
}

// ---------------------------------------------------------------------------
// Fused attention core, v2: XOR-swizzled tile (k4 ^ (t&7)) for conflict-free
// column AND row access. Logits: warp = (head-pair, K-half), lane = t, no
// reductions. u-phase: thread = (k4, t-half), 8-head register accumulators,
// tile read exactly once; pair-reduce through reused s_p region.
// ---------------------------------------------------------------------------
__global__ __launch_bounds__(256) void attn_core(
    const float* __restrict__ tgt,
    const float* __restrict__ Q,
    const float* __restrict__ P,
    const void* __restrict__ mask_raw,
    const int* __restrict__ mask_mode,
    const float* __restrict__ ipb,
    float* __restrict__ U,
    int* __restrict__ allm)
{
    extern __shared__ float sm[];
    float4* tile4 = (float4*)sm;      // 4096 f4 = 64KB, swizzled
    float*  s_p   = sm + 16384;       // 4096 (reused as reduction buffer)
    float*  s_la  = sm + 20480;       // 2 * 256 partial logits
    float*  s_a   = sm + 20992;       // 256 softmax weights
    float*  s_c   = sm + 21248;       // 8   q.b_k per head
    float*  s_m   = sm + 21256;       // 32  mask flags
    float*  s_am  = sm + 21288;       // 1   all-masked

    const int i    = blockIdx.x;
    const int tid  = threadIdx.x;
    const int lane = tid & 31, w = tid >> 5;

    // tile fill with swizzle: element (t, k4) -> tile4[t*128 + (k4 ^ (t&7))]
    const float4* tg = (const float4*)(tgt + (size_t)i * (TT * DM));
    #pragma unroll
    for (int r = 0; r < 16; r++) {
        int g = tid + 256 * r;
        int t = g >> 7, k4 = g & 127;
        tile4[(t << 7) + (k4 ^ (t & 7))] = tg[g];
    }
    // p fill (linear)
    const float4* pg = (const float4*)(P + (size_t)i * (NH * DM));
    float4* sp4 = (float4*)s_p;
    #pragma unroll
    for (int r = 0; r < 4; r++) sp4[tid + 256 * r] = pg[tid + 256 * r];

    // c[h] = q_h . b_k_h
    {
        const float* qr = Q   + (size_t)i * DM + w * DH;
        const float* br = ipb + DM + w * DH;
        float cs = qr[lane] * br[lane] + qr[lane + 32] * br[lane + 32];
        #pragma unroll
        for (int off = 16; off; off >>= 1)
            cs += __shfl_down_sync(0xffffffffu, cs, off);
        if (lane == 0) s_c[w] = cs;
    }
    // mask (warp 0), dtype-adaptive
    if (w == 0) {
        const int mode = *mask_mode;
        unsigned mv;
        if (mode == 0)      mv = ((const unsigned char*)mask_raw)[(size_t)i * TT + lane];
        else if (mode == 1) mv = ((const unsigned*)mask_raw)[(size_t)i * TT + lane] != 0u;
        else                mv = ((const float*)mask_raw)[(size_t)i * TT + lane] != 0.f;
        s_m[lane] = mv ? 1.f : 0.f;
        unsigned bal = __ballot_sync(0xffffffffu, mv != 0);
        if (lane == 0) {
            int am = (bal == 0xffffffffu) ? 1 : 0;
            s_am[0] = (float)am;
            allm[i] = am;
        }
    }
    __syncthreads();

    // logits: warp w -> heads {hp, hp+1}, K-half kb; lane = t
    {
        const int hp = (w & 3) << 1;
        const int kb = (w >> 2) << 6;
        const float4* p0 = (const float4*)(s_p + hp * DM);
        const float4* p1 = (const float4*)(s_p + (hp + 1) * DM);
        const int tb = lane << 7, cx = lane & 7;
        float s0 = 0.f, s1 = 0.f;
        #pragma unroll 8
        for (int k4 = kb; k4 < kb + 64; k4++) {
            float4 tv = tile4[tb + (k4 ^ cx)];
            float4 q0 = p0[k4], q1 = p1[k4];
            s0 += tv.x * q0.x + tv.y * q0.y + tv.z * q0.z + tv.w * q0.w;
            s1 += tv.x * q1.x + tv.y * q1.y + tv.z * q1.z + tv.w * q1.w;
        }
        s_la[(w >> 2) * 256 + hp * 32 + lane]       = s0;
        s_la[(w >> 2) * 256 + (hp + 1) * 32 + lane] = s1;
    }
    __syncthreads();

    // softmax over t (warp w = head w); scale 1/sqrt(64)
    {
        const float am = s_am[0];
        float l = s_la[w * 32 + lane] + s_la[256 + w * 32 + lane] + s_c[w];
        const bool inv = (s_m[lane] != 0.f) && (am == 0.f);
        l = inv ? -1e30f : l * 0.125f;
        float m = l;
        #pragma unroll
        for (int off = 16; off; off >>= 1)
            m = fmaxf(m, __shfl_xor_sync(0xffffffffu, m, off));
        float e = inv ? 0.f : __expf(l - m);
        float s = e;
        #pragma unroll
        for (int off = 16; off; off >>= 1)
            s += __shfl_xor_sync(0xffffffffu, s, off);
        s_a[w * 32 + lane] = e / s;
    }
    __syncthreads();

    // u[h][k4] = sum_t a[h][t] * tile[t][k4]; thread = (k4, t-half)
    {
        const int k4 = tid & 127, half = tid >> 7;
        float4 acc[NH];
        #pragma unroll
        for (int h = 0; h < NH; h++) acc[h] = make_float4(0.f, 0.f, 0.f, 0.f);
        const int t0 = half << 4;
        #pragma unroll
        for (int j = 0; j < 16; j++) {
            const int t = t0 + j;
            float4 tv = tile4[(t << 7) + (k4 ^ (t & 7))];
            #pragma unroll
            for (int h = 0; h < NH; h++) {
                float a = s_a[(h << 5) + t];
                acc[h].x += a * tv.x; acc[h].y += a * tv.y;
                acc[h].z += a * tv.z; acc[h].w += a * tv.w;
            }
        }
        float4* red = (float4*)s_p;   // s_p is dead after logits
        if (half) {
            #pragma unroll
            for (int h = 0; h < NH; h++) red[(h << 7) + k4] = acc[h];
        }
        __syncthreads();
        if (!half) {
            float4* u4 = (float4*)(U + (size_t)i * (NH * DM));
            #pragma unroll
            for (int h = 0; h < NH; h++) {
                float4 rv = red[(h << 7) + k4];
                u4[(h << 7) + k4] = make_float4(acc[h].x + rv.x, acc[h].y + rv.y,
                                                acc[h].z + rv.z, acc[h].w + rv.w);
            }
        }
    }
}

extern "C" void kernel_launch(void* const* d_in, const int* in_sizes, int n_in,
                              void* d_out, int out_size) {
    const float* src  = (const float*)d_in[0];
    const float* tgt  = (const float*)d_in[1];
    const void*  mask = d_in[2];
    const float* ipw  = (const float*)d_in[3];   // (1536,512)
    const float* ipb  = (const float*)d_in[4];   // (1536,)
    const float* opw  = (const float*)d_in[5];   // (512,512)
    const float* opb  = (const float*)d_in[6];   // (512,)
    float*       out  = (float*)d_out;

    float *Q, *P, *U, *CTX; int *AM, *MODE;
    cudaGetSymbolAddress((void**)&Q,    g_Q);
    cudaGetSymbolAddress((void**)&P,    g_P);
    cudaGetSymbolAddress((void**)&U,    g_U);
    cudaGetSymbolAddress((void**)&CTX,  g_CTX);
    cudaGetSymbolAddress((void**)&AM,   g_AM);
    cudaGetSymbolAddress((void**)&MODE, g_MaskMode);

    // 0) detect mask dtype
    detect_mask_kernel<<<1, 256>>>((const unsigned*)mask, 16384, MODE);

    // 1) Q = src @ Wq^T + bq                (2048,512)x(512,512)
    gemm128<true, false><<<dim3(16, 8, 1), 128>>>(
        src, 512, 0, ipw, 512, 0, Q, 512, 0, ipb, 0, 512, nullptr);

    // 2) P[:,h,:] = Q[:,h*64:+64] @ Wk_h    per-head (2048,64)x(64,512)
    gemm128<false, false><<<dim3(16, 8, 8), 128>>>(
        Q, 512, 64, ipw + 512 * 512, 512, 64 * 512,
        P, 4096, 512, nullptr, 0, 64, nullptr);

    // 3) fused attention: logits -> softmax -> U
    const int smem = 21292 * 4;
    cudaFuncSetAttribute(attn_core, cudaFuncAttributeMaxDynamicSharedMemorySize, smem);
    attn_core<<<2048, 256, smem>>>(tgt, Q, P, mask, MODE, ipb, U, AM);

    // 4) ctx[:,h*64:+64] = U[:,h,:] @ Wv_h^T + bv   per-head (2048,512)x(512,64)
    gemm128<true, false><<<dim3(16, 1, 8), 128>>>(
        U, 4096, 512, ipw + 1024 * 512, 512, 64 * 512,
        CTX, 512, 64, ipb + 1024, 64, 512, nullptr);

    // 5) out = ctx @ Wo^T + bo, zeroing all-masked rows
    gemm128<true, true><<<dim3(16, 8, 1), 128>>>(
        CTX, 512, 0, opw, 512, 0, out, 512, 0, opb, 0, 512, AM);
}

// round 6
// speedup vs baseline: 1.7602x; 1.1964x over previous
#include <cuda_runtime.h>
#include <cuda_bf16.h>
#include <cstdint>

// Problem constants
#define NPOS 2048   // B*S
#define DM   512
#define NH   8
#define DH   64
#define TT   32

// Scratch (device globals)
__device__ float g_Q  [NPOS * DM];
__device__ float g_P  [NPOS * NH * DM];
__device__ float g_U  [NPOS * NH * DM];
__device__ float g_CTX[NPOS * DM];
__device__ float g_WKT[NH * DM * DH];   // W_k^T per head: [h][n=512][k=64]
__device__ int   g_AM [NPOS];
__device__ int   g_MaskMode;

// ======================= helpers ===========================================
__device__ __forceinline__ uint32_t smem_u32(const void* p) {
    uint32_t a;
    asm("{ .reg .u64 t; cvta.to.shared.u64 t, %1; cvt.u32.u64 %0, t; }"
        : "=r"(a) : "l"(p));
    return a;
}
__device__ __forceinline__ void ldm_x4(uint32_t* r, uint32_t addr) {
    asm volatile("ldmatrix.sync.aligned.m8n8.x4.shared.b16 {%0,%1,%2,%3}, [%4];"
                 : "=r"(r[0]), "=r"(r[1]), "=r"(r[2]), "=r"(r[3]) : "r"(addr));
}
__device__ __forceinline__ void mma_bf16(float* d, const uint32_t* a,
                                         uint32_t b0, uint32_t b1) {
    asm volatile(
        "mma.sync.aligned.m16n8k16.row.col.f32.bf16.bf16.f32 "
        "{%0,%1,%2,%3}, {%4,%5,%6,%7}, {%8,%9}, {%0,%1,%2,%3};"
        : "+f"(d[0]), "+f"(d[1]), "+f"(d[2]), "+f"(d[3])
        : "r"(a[0]), "r"(a[1]), "r"(a[2]), "r"(a[3]), "r"(b0), "r"(b1));
}
__device__ __forceinline__ unsigned pack_bf2(__nv_bfloat16 a, __nv_bfloat16 b) {
    __nv_bfloat162 t; t.x = a; t.y = b;
    return *reinterpret_cast<unsigned*>(&t);
}
// fp32x4 -> (hi,lo) bf16x4 as uint2 pairs
__device__ __forceinline__ void split4(float4 v, uint2& hi, uint2& lo) {
    __nv_bfloat16 hx = __float2bfloat16(v.x), hy = __float2bfloat16(v.y);
    __nv_bfloat16 hz = __float2bfloat16(v.z), hw = __float2bfloat16(v.w);
    __nv_bfloat16 lx = __float2bfloat16(v.x - __bfloat162float(hx));
    __nv_bfloat16 ly = __float2bfloat16(v.y - __bfloat162float(hy));
    __nv_bfloat16 lz = __float2bfloat16(v.z - __bfloat162float(hz));
    __nv_bfloat16 lw = __float2bfloat16(v.w - __bfloat162float(hw));
    hi = make_uint2(pack_bf2(hx, hy), pack_bf2(hz, hw));
    lo = make_uint2(pack_bf2(lx, ly), pack_bf2(lz, lw));
}

// ======================= mask dtype detection ==============================
__global__ void detect_mask_kernel(const unsigned* __restrict__ w, int nwords,
                                   int* __restrict__ mode) {
    __shared__ int flags[2];
    if (threadIdx.x < 2) flags[threadIdx.x] = 0;
    __syncthreads();
    for (int j = threadIdx.x; j < nwords; j += blockDim.x) {
        unsigned v = w[j];
        if (v == 0x3F800000u)      atomicOr(&flags[0], 1);
        else if (v > 1u)           atomicOr(&flags[1], 1);
    }
    __syncthreads();
    if (threadIdx.x == 0)
        *mode = flags[0] ? 2 : (flags[1] ? 0 : 1);
}

// ======================= W_k transpose =====================================
__global__ void transpose_wk(const float* __restrict__ ipw, float* __restrict__ wkt) {
    __shared__ float t[32][33];
    const int h = blockIdx.z, kb = blockIdx.y * 32, nb = blockIdx.x * 32;
    const int x = threadIdx.x, y = threadIdx.y;
    for (int i = y; i < 32; i += 8)
        t[i][x] = ipw[(size_t)(512 + h * 64 + kb + i) * 512 + nb + x];
    __syncthreads();
    for (int i = y; i < 32; i += 8)
        wkt[(size_t)h * (512 * 64) + (size_t)(nb + i) * 64 + kb + x] = t[x][i];
}

// ======================= HMMA GEMM (mma.sync bf16 split) ===================
// C[M,N] = A[M,K] @ B[N,K]^T + bias, fp32 I/O; internally bf16 2-term split
// (hi*hi + hi*lo + lo*hi) -> rel err ~1e-5. CTA tile 128x64, BK=32, 8 warps
// as 4(M) x 2(N), warp tile 32x32. Smem rows padded to 80B: stride = 20 banks
// so the 8 ldmatrix rows cover all 32 banks (conflict-free). Double-buffered.
template <bool ZMASK>
__global__ __launch_bounds__(256) void hmma_gemm(
    const float* __restrict__ A, int lda, int aoz,
    const float* __restrict__ B, int ldb, int boz,
    float* __restrict__ C, int ldc, int coz,
    const float* __restrict__ bias, int bioz,
    int K, const int* __restrict__ rmask)
{
    constexpr int RS   = 80;                 // smem row stride (bytes)
    constexpr int AB   = 128 * RS;           // 10240
    constexpr int BBY  = 64 * RS;            // 5120
    constexpr int STG  = 2 * AB + 2 * BBY;   // 30720 per buffer

    extern __shared__ char smem[];

    const int z = blockIdx.z;
    A += (size_t)z * aoz;  B += (size_t)z * boz;  C += (size_t)z * coz;
    if (bias) bias += (size_t)z * bioz;
    const int m0 = blockIdx.x * 128, n0 = blockIdx.y * 64;

    const int tid = threadIdx.x, lane = tid & 31, wid = tid >> 5;
    const int wm = wid & 3, wn = wid >> 2;     // warp coords (4M x 2N)

    // staging thread mapping
    const int ar = tid >> 1, ac = tid & 1;     // A: row, 16-float half
    const int br = tid >> 2, bc = tid & 3;     // B: row, 8-float eighth

    // ldmatrix lane addressing
    const int g  = lane >> 3, lr = lane & 7;
    const int grow = (g & 1) * 8 + lr;         // row within 16
    const int gk   = (g >> 1) * 16;            // k-byte offset within k16

    float4 pa[4], pb[2];
    float acc[2][4][4] = {};

    const int nst = K >> 5;
    // prologue gmem loads (stage 0)
    #pragma unroll
    for (int j = 0; j < 4; j++)
        pa[j] = *(const float4*)&A[(size_t)(m0 + ar) * lda + ac * 16 + j * 4];
    #pragma unroll
    for (int j = 0; j < 2; j++)
        pb[j] = *(const float4*)&B[(size_t)(n0 + br) * ldb + bc * 8 + j * 4];

    for (int s = 0; s < nst; s++) {
        char* buf = smem + (s & 1) * STG;
        char* ah = buf;            char* al = buf + AB;
        char* bh = buf + 2 * AB;   char* bl = bh + BBY;

        // store staged regs -> smem (fp32 -> hi/lo bf16)
        #pragma unroll
        for (int j = 0; j < 4; j++) {
            uint2 hi, lo; split4(pa[j], hi, lo);
            const int off = ar * RS + ac * 32 + j * 8;
            *(uint2*)(ah + off) = hi; *(uint2*)(al + off) = lo;
        }
        #pragma unroll
        for (int j = 0; j < 2; j++) {
            uint2 hi, lo; split4(pb[j], hi, lo);
            const int off = br * RS + bc * 16 + j * 8;
            *(uint2*)(bh + off) = hi; *(uint2*)(bl + off) = lo;
        }
        __syncthreads();

        // prefetch next stage
        if (s + 1 < nst) {
            const int kt = (s + 1) << 5;
            #pragma unroll
            for (int j = 0; j < 4; j++)
                pa[j] = *(const float4*)&A[(size_t)(m0 + ar) * lda + kt + ac * 16 + j * 4];
            #pragma unroll
            for (int j = 0; j < 2; j++)
                pb[j] = *(const float4*)&B[(size_t)(n0 + br) * ldb + kt + bc * 8 + j * 4];
        }

        // compute: 2 k16 sub-steps
        const uint32_t ahs = smem_u32(ah), als = smem_u32(al);
        const uint32_t bhs = smem_u32(bh), bls = smem_u32(bl);
        #pragma unroll
        for (int kk = 0; kk < 2; kk++) {
            const int kb = kk * 32 + gk;       // byte offset in row
            uint32_t a_hi[2][4], a_lo[2][4], b_hi[2][4], b_lo[2][4];
            #pragma unroll
            for (int mt = 0; mt < 2; mt++) {
                const uint32_t ro = (wm * 32 + mt * 16 + grow) * RS + kb;
                ldm_x4(a_hi[mt], ahs + ro);
                ldm_x4(a_lo[mt], als + ro);
            }
            #pragma unroll
            for (int ng = 0; ng < 2; ng++) {
                const uint32_t ro = (wn * 32 + ng * 16 + grow) * RS + kb;
                ldm_x4(b_hi[ng], bhs + ro);
                ldm_x4(b_lo[ng], bls + ro);
            }
            #pragma unroll
            for (int mt = 0; mt < 2; mt++)
                #pragma unroll
                for (int nt = 0; nt < 4; nt++) {
                    const int ng = nt >> 1, sel = nt & 1;
                    const uint32_t bh0 = b_hi[ng][sel], bh1 = b_hi[ng][sel + 2];
                    const uint32_t bl0 = b_lo[ng][sel], bl1 = b_lo[ng][sel + 2];
                    mma_bf16(acc[mt][nt], a_hi[mt], bh0, bh1);
                    mma_bf16(acc[mt][nt], a_hi[mt], bl0, bl1);
                    mma_bf16(acc[mt][nt], a_lo[mt], bh0, bh1);
                }
        }
        __syncthreads();
    }

    // epilogue: fragment layout d0,d1 -> (row, col..col+1); d2,d3 -> row+8
    const int qr = lane >> 2, qc = (lane & 3) * 2;
    #pragma unroll
    for (int mt = 0; mt < 2; mt++) {
        const int r0 = m0 + wm * 32 + mt * 16 + qr;
        const bool z0 = ZMASK ? (rmask[r0] != 0)     : false;
        const bool z1 = ZMASK ? (rmask[r0 + 8] != 0) : false;
        #pragma unroll
        for (int nt = 0; nt < 4; nt++) {
            const int c = n0 + wn * 32 + nt * 8 + qc;
            float b0 = 0.f, b1 = 0.f;
            if (bias) { b0 = bias[c]; b1 = bias[c + 1]; }
            float2 v0 = make_float2(acc[mt][nt][0] + b0, acc[mt][nt][1] + b1);
            float2 v1 = make_float2(acc[mt][nt][2] + b0, acc[mt][nt][3] + b1);
            if (z0) v0 = make_float2(0.f, 0.f);
            if (z1) v1 = make_float2(0.f, 0.f);
            *(float2*)&C[(size_t)r0 * ldc + c]       = v0;
            *(float2*)&C[(size_t)(r0 + 8) * ldc + c] = v1;
        }
    }
}

// ======================= fused attention core (unchanged) ==================
__global__ __launch_bounds__(256) void attn_core(
    const float* __restrict__ tgt,
    const float* __restrict__ Q,
    const float* __restrict__ P,
    const void* __restrict__ mask_raw,
    const int* __restrict__ mask_mode,
    const float* __restrict__ ipb,
    float* __restrict__ U,
    int* __restrict__ allm)
{
    extern __shared__ float sm[];
    float4* tile4 = (float4*)sm;
    float*  s_p   = sm + 16384;
    float*  s_la  = sm + 20480;
    float*  s_a   = sm + 20992;
    float*  s_c   = sm + 21248;
    float*  s_m   = sm + 21256;
    float*  s_am  = sm + 21288;

    const int i    = blockIdx.x;
    const int tid  = threadIdx.x;
    const int lane = tid & 31, w = tid >> 5;

    const float4* tg = (const float4*)(tgt + (size_t)i * (TT * DM));
    #pragma unroll
    for (int r = 0; r < 16; r++) {
        int gg = tid + 256 * r;
        int t = gg >> 7, k4 = gg & 127;
        tile4[(t << 7) + (k4 ^ (t & 7))] = tg[gg];
    }
    const float4* pg = (const float4*)(P + (size_t)i * (NH * DM));
    float4* sp4 = (float4*)s_p;
    #pragma unroll
    for (int r = 0; r < 4; r++) sp4[tid + 256 * r] = pg[tid + 256 * r];

    {
        const float* qr = Q   + (size_t)i * DM + w * DH;
        const float* br = ipb + DM + w * DH;
        float cs = qr[lane] * br[lane] + qr[lane + 32] * br[lane + 32];
        #pragma unroll
        for (int off = 16; off; off >>= 1)
            cs += __shfl_down_sync(0xffffffffu, cs, off);
        if (lane == 0) s_c[w] = cs;
    }
    if (w == 0) {
        const int mode = *mask_mode;
        unsigned mv;
        if (mode == 0)      mv = ((const unsigned char*)mask_raw)[(size_t)i * TT + lane];
        else if (mode == 1) mv = ((const unsigned*)mask_raw)[(size_t)i * TT + lane] != 0u;
        else                mv = ((const float*)mask_raw)[(size_t)i * TT + lane] != 0.f;
        s_m[lane] = mv ? 1.f : 0.f;
        unsigned bal = __ballot_sync(0xffffffffu, mv != 0);
        if (lane == 0) {
            int am = (bal == 0xffffffffu) ? 1 : 0;
            s_am[0] = (float)am;
            allm[i] = am;
        }
    }
    __syncthreads();

    {
        const int hp = (w & 3) << 1;
        const int kb = (w >> 2) << 6;
        const float4* p0 = (const float4*)(s_p + hp * DM);
        const float4* p1 = (const float4*)(s_p + (hp + 1) * DM);
        const int tb = lane << 7, cx = lane & 7;
        float s0 = 0.f, s1 = 0.f;
        #pragma unroll 8
        for (int k4 = kb; k4 < kb + 64; k4++) {
            float4 tv = tile4[tb + (k4 ^ cx)];
            float4 q0 = p0[k4], q1 = p1[k4];
            s0 += tv.x * q0.x + tv.y * q0.y + tv.z * q0.z + tv.w * q0.w;
            s1 += tv.x * q1.x + tv.y * q1.y + tv.z * q1.z + tv.w * q1.w;
        }
        s_la[(w >> 2) * 256 + hp * 32 + lane]       = s0;
        s_la[(w >> 2) * 256 + (hp + 1) * 32 + lane] = s1;
    }
    __syncthreads();

    {
        const float am = s_am[0];
        float l = s_la[w * 32 + lane] + s_la[256 + w * 32 + lane] + s_c[w];
        const bool inv = (s_m[lane] != 0.f) && (am == 0.f);
        l = inv ? -1e30f : l * 0.125f;
        float m = l;
        #pragma unroll
        for (int off = 16; off; off >>= 1)
            m = fmaxf(m, __shfl_xor_sync(0xffffffffu, m, off));
        float e = inv ? 0.f : __expf(l - m);
        float s = e;
        #pragma unroll
        for (int off = 16; off; off >>= 1)
            s += __shfl_xor_sync(0xffffffffu, s, off);
        s_a[w * 32 + lane] = e / s;
    }
    __syncthreads();

    {
        const int k4 = tid & 127, half = tid >> 7;
        float4 acc[NH];
        #pragma unroll
        for (int h = 0; h < NH; h++) acc[h] = make_float4(0.f, 0.f, 0.f, 0.f);
        const int t0 = half << 4;
        #pragma unroll
        for (int j = 0; j < 16; j++) {
            const int t = t0 + j;
            float4 tv = tile4[(t << 7) + (k4 ^ (t & 7))];
            #pragma unroll
            for (int h = 0; h < NH; h++) {
                float a = s_a[(h << 5) + t];
                acc[h].x += a * tv.x; acc[h].y += a * tv.y;
                acc[h].z += a * tv.z; acc[h].w += a * tv.w;
            }
        }
        float4* red = (float4*)s_p;
        if (half) {
            #pragma unroll
            for (int h = 0; h < NH; h++) red[(h << 7) + k4] = acc[h];
        }
        __syncthreads();
        if (!half) {
            float4* u4 = (float4*)(U + (size_t)i * (NH * DM));
            #pragma unroll
            for (int h = 0; h < NH; h++) {
                float4 rv = red[(h << 7) + k4];
                u4[(h << 7) + k4] = make_float4(acc[h].x + rv.x, acc[h].y + rv.y,
                                                acc[h].z + rv.z, acc[h].w + rv.w);
            }
        }
    }
}

// ======================= launch ============================================
extern "C" void kernel_launch(void* const* d_in, const int* in_sizes, int n_in,
                              void* d_out, int out_size) {
    const float* src  = (const float*)d_in[0];
    const float* tgt  = (const float*)d_in[1];
    const void*  mask = d_in[2];
    const float* ipw  = (const float*)d_in[3];
    const float* ipb  = (const float*)d_in[4];
    const float* opw  = (const float*)d_in[5];
    const float* opb  = (const float*)d_in[6];
    float*       out  = (float*)d_out;

    float *Q, *P, *U, *CTX, *WKT; int *AM, *MODE;
    cudaGetSymbolAddress((void**)&Q,    g_Q);
    cudaGetSymbolAddress((void**)&P,    g_P);
    cudaGetSymbolAddress((void**)&U,    g_U);
    cudaGetSymbolAddress((void**)&CTX,  g_CTX);
    cudaGetSymbolAddress((void**)&WKT,  g_WKT);
    cudaGetSymbolAddress((void**)&AM,   g_AM);
    cudaGetSymbolAddress((void**)&MODE, g_MaskMode);

    const int SMG = 2 * 30720;   // 60 KB double-buffered
    cudaFuncSetAttribute(hmma_gemm<false>, cudaFuncAttributeMaxDynamicSharedMemorySize, SMG);
    cudaFuncSetAttribute(hmma_gemm<true>,  cudaFuncAttributeMaxDynamicSharedMemorySize, SMG);

    // 0) mask dtype + W_k transpose
    detect_mask_kernel<<<1, 256>>>((const unsigned*)mask, 16384, MODE);
    transpose_wk<<<dim3(16, 2, 8), dim3(32, 8)>>>(ipw, WKT);

    // 1) Q = src @ Wq^T + bq               (2048,512)x(512,512)^T
    hmma_gemm<false><<<dim3(16, 8, 1), 256, SMG>>>(
        src, 512, 0, ipw, 512, 0, Q, 512, 0, ipb, 0, 512, nullptr);

    // 2) P[:,h,:] = Q_h @ WkT_h^T          per-head (2048,64)x(512,64)^T
    hmma_gemm<false><<<dim3(16, 8, 8), 256, SMG>>>(
        Q, 512, 64, WKT, 64, 512 * 64,
        P, 4096, 512, nullptr, 0, 64, nullptr);

    // 3) fused attention: logits -> softmax -> U
    const int smemA = 21292 * 4;
    cudaFuncSetAttribute(attn_core, cudaFuncAttributeMaxDynamicSharedMemorySize, smemA);
    attn_core<<<2048, 256, smemA>>>(tgt, Q, P, mask, MODE, ipb, U, AM);

    // 4) ctx[:,h*64:+64] = U_h @ Wv_h^T + bv   per-head (2048,512)x(64,512)^T
    hmma_gemm<false><<<dim3(16, 1, 8), 256, SMG>>>(
        U, 4096, 512, ipw + 1024 * 512, 512, 64 * 512,
        CTX, 512, 64, ipb + 1024, 64, 512, nullptr);

    // 5) out = ctx @ Wo^T + bo, zeroing all-masked rows
    hmma_gemm<true><<<dim3(16, 8, 1), 256, SMG>>>(
        CTX, 512, 0, opw, 512, 0, out, 512, 0, opb, 0, 512, AM);
}

// round 7
// speedup vs baseline: 1.9923x; 1.1318x over previous
#include <cuda_runtime.h>
#include <cuda_bf16.h>
#include <cstdint>

// Problem constants
#define NPOS 2048   // B*S
#define DM   512
#define NH   8
#define DH   64
#define TT   32

typedef __nv_bfloat16 bf16;

// Scratch (device globals). bf16 planes force 16B alignment for uint4 access.
__device__ float g_Q  [NPOS * DM];
__device__ float g_P  [NPOS * NH * DM];
__device__ int   g_AM [NPOS];
__device__ int   g_MaskMode;
__device__ __align__(16) bf16 g_SRCh[NPOS * DM],      g_SRCl[NPOS * DM];
__device__ __align__(16) bf16 g_Qh  [NPOS * DM],      g_Ql  [NPOS * DM];
__device__ __align__(16) bf16 g_Uh  [NPOS * NH * DM], g_Ul  [NPOS * NH * DM];
__device__ __align__(16) bf16 g_CTXh[NPOS * DM],      g_CTXl[NPOS * DM];
__device__ __align__(16) bf16 g_WQh [DM * DM],        g_WQl [DM * DM];
__device__ __align__(16) bf16 g_WKTh[NH * DM * DH],   g_WKTl[NH * DM * DH];
__device__ __align__(16) bf16 g_WVh [DM * DM],        g_WVl [DM * DM];
__device__ __align__(16) bf16 g_WOh [DM * DM],        g_WOl [DM * DM];

// ======================= helpers ===========================================
__device__ __forceinline__ uint32_t smem_u32(const void* p) {
    uint32_t a;
    asm("{ .reg .u64 t; cvta.to.shared.u64 t, %1; cvt.u32.u64 %0, t; }"
        : "=r"(a) : "l"(p));
    return a;
}
__device__ __forceinline__ void ldm_x4(uint32_t* r, uint32_t addr) {
    asm volatile("ldmatrix.sync.aligned.m8n8.x4.shared.b16 {%0,%1,%2,%3}, [%4];"
                 : "=r"(r[0]), "=r"(r[1]), "=r"(r[2]), "=r"(r[3]) : "r"(addr));
}
__device__ __forceinline__ void mma_bf16(float* d, const uint32_t* a,
                                         uint32_t b0, uint32_t b1) {
    asm volatile(
        "mma.sync.aligned.m16n8k16.row.col.f32.bf16.bf16.f32 "
        "{%0,%1,%2,%3}, {%4,%5,%6,%7}, {%8,%9}, {%0,%1,%2,%3};"
        : "+f"(d[0]), "+f"(d[1]), "+f"(d[2]), "+f"(d[3])
        : "r"(a[0]), "r"(a[1]), "r"(a[2]), "r"(a[3]), "r"(b0), "r"(b1));
}
__device__ __forceinline__ unsigned pack_bf2(bf16 a, bf16 b) {
    __nv_bfloat162 t; t.x = a; t.y = b;
    return *reinterpret_cast<unsigned*>(&t);
}
__device__ __forceinline__ void split4(float4 v, uint2& hi, uint2& lo) {
    bf16 hx = __float2bfloat16(v.x), hy = __float2bfloat16(v.y);
    bf16 hz = __float2bfloat16(v.z), hw = __float2bfloat16(v.w);
    bf16 lx = __float2bfloat16(v.x - __bfloat162float(hx));
    bf16 ly = __float2bfloat16(v.y - __bfloat162float(hy));
    bf16 lz = __float2bfloat16(v.z - __bfloat162float(hz));
    bf16 lw = __float2bfloat16(v.w - __bfloat162float(hw));
    hi = make_uint2(pack_bf2(hx, hy), pack_bf2(hz, hw));
    lo = make_uint2(pack_bf2(lx, ly), pack_bf2(lz, lw));
}
__device__ __forceinline__ void split2_store(float x, float y,
                                             bf16* hi, bf16* lo, size_t off) {
    bf16 hx = __float2bfloat16(x), hy = __float2bfloat16(y);
    bf16 lx = __float2bfloat16(x - __bfloat162float(hx));
    bf16 ly = __float2bfloat16(y - __bfloat162float(hy));
    *(uint32_t*)&hi[off] = pack_bf2(hx, hy);
    *(uint32_t*)&lo[off] = pack_bf2(lx, ly);
}

// ======================= one-shot split / transpose ========================
__global__ void split_f32(const float* __restrict__ x, bf16* __restrict__ hi,
                          bf16* __restrict__ lo, int n4) {
    int i = blockIdx.x * 256 + threadIdx.x;
    if (i < n4) {
        float4 v = ((const float4*)x)[i];
        uint2 h, l; split4(v, h, l);
        ((uint2*)hi)[i] = h; ((uint2*)lo)[i] = l;
    }
}
// wkt[h][n][k] = ipw[512 + h*64 + k][n], split to hi/lo
__global__ void transpose_wk_split(const float* __restrict__ ipw,
                                   bf16* __restrict__ hi, bf16* __restrict__ lo) {
    __shared__ float t[32][33];
    const int h = blockIdx.z, kb = blockIdx.y * 32, nb = blockIdx.x * 32;
    const int x = threadIdx.x, y = threadIdx.y;
    for (int i = y; i < 32; i += 8)
        t[i][x] = ipw[(size_t)(512 + h * 64 + kb + i) * 512 + nb + x];
    __syncthreads();
    for (int i = y; i < 32; i += 8) {
        float v = t[x][i];
        size_t o = (size_t)h * (512 * 64) + (size_t)(nb + i) * 64 + kb + x;
        bf16 bh = __float2bfloat16(v);
        hi[o] = bh;
        lo[o] = __float2bfloat16(v - __bfloat162float(bh));
    }
}

// ======================= mask dtype detection ==============================
__global__ void detect_mask_kernel(const unsigned* __restrict__ w, int nwords,
                                   int* __restrict__ mode) {
    __shared__ int flags[2];
    if (threadIdx.x < 2) flags[threadIdx.x] = 0;
    __syncthreads();
    for (int j = threadIdx.x; j < nwords; j += blockDim.x) {
        unsigned v = w[j];
        if (v == 0x3F800000u)      atomicOr(&flags[0], 1);
        else if (v > 1u)           atomicOr(&flags[1], 1);
    }
    __syncthreads();
    if (threadIdx.x == 0)
        *mode = flags[0] ? 2 : (flags[1] ? 0 : 1);
}

// ======================= HMMA GEMM (pre-split bf16 operands) ===============
// C[M,N] = A[M,K] @ B[N,K]^T + bias; A,B given as bf16 hi/lo planes.
// Split product: hi*hi + hi*lo + lo*hi (fp32 accum). CTA tile 128x64, BK=32,
// 8 warps = 4(M) x 2(N). Smem rows padded to 80B (conflict-free ldmatrix).
// EMIT bit0: write fp32 C. EMIT bit1: write bf16 hi/lo C planes.
template <int EMIT, bool ZMASK>
__global__ __launch_bounds__(256) void hmma_gemm(
    const bf16* __restrict__ Ahi, const bf16* __restrict__ Alo, int lda, int aoz,
    const bf16* __restrict__ Bhi, const bf16* __restrict__ Blo, int ldb, int boz,
    float* __restrict__ C, bf16* __restrict__ Chi, bf16* __restrict__ Clo,
    int ldc, int coz,
    const float* __restrict__ bias, int bioz,
    int K, const int* __restrict__ rmask)
{
    constexpr int RS  = 80;                  // smem row stride (bytes)
    constexpr int APL = 128 * RS;            // A plane 10240
    constexpr int BPL = 64 * RS;             // B plane 5120
    constexpr int STG = 2 * APL + 2 * BPL;   // 30720 per buffer

    extern __shared__ char smem[];

    const int z = blockIdx.z;
    Ahi += (size_t)z * aoz;  Alo += (size_t)z * aoz;
    Bhi += (size_t)z * boz;  Blo += (size_t)z * boz;
    const int m0 = blockIdx.x * 128, n0 = blockIdx.y * 64;

    const int tid = threadIdx.x, lane = tid & 31, wid = tid >> 5;
    const int wm = wid & 3, wn = wid >> 2;

    // staging maps: A has 512 16B-chunks (2/thread), B has 256 (1/thread)
    const int ar0 = tid >> 2,        ac0 = tid & 3;
    const int ar1 = (tid + 256) >> 2, ac1 = ac0;    // (tid+256)&3 == tid&3
    const int br  = tid >> 2,        bc  = tid & 3;

    // ldmatrix lane addressing
    const int g = lane >> 3, lr = lane & 7;
    const int grow = (g & 1) * 8 + lr;
    const int gk   = (g >> 1) * 16;

    uint4 pah[2], pal[2], pbh, pbl;
    float acc[2][4][4] = {};

    const int nst = K >> 5;
    // prologue (kt = 0)
    pah[0] = *(const uint4*)&Ahi[(size_t)(m0 + ar0) * lda + ac0 * 8];
    pah[1] = *(const uint4*)&Ahi[(size_t)(m0 + ar1) * lda + ac1 * 8];
    pal[0] = *(const uint4*)&Alo[(size_t)(m0 + ar0) * lda + ac0 * 8];
    pal[1] = *(const uint4*)&Alo[(size_t)(m0 + ar1) * lda + ac1 * 8];
    pbh    = *(const uint4*)&Bhi[(size_t)(n0 + br) * ldb + bc * 8];
    pbl    = *(const uint4*)&Blo[(size_t)(n0 + br) * ldb + bc * 8];

    for (int s = 0; s < nst; s++) {
        char* buf = smem + (s & 1) * STG;
        char* ah = buf;            char* al = buf + APL;
        char* bh = buf + 2 * APL;  char* bl = bh + BPL;

        *(uint4*)(ah + ar0 * RS + ac0 * 16) = pah[0];
        *(uint4*)(ah + ar1 * RS + ac1 * 16) = pah[1];
        *(uint4*)(al + ar0 * RS + ac0 * 16) = pal[0];
        *(uint4*)(al + ar1 * RS + ac1 * 16) = pal[1];
        *(uint4*)(bh + br * RS + bc * 16)   = pbh;
        *(uint4*)(bl + br * RS + bc * 16)   = pbl;
        __syncthreads();

        if (s + 1 < nst) {
            const int kt = (s + 1) << 5;
            pah[0] = *(const uint4*)&Ahi[(size_t)(m0 + ar0) * lda + kt + ac0 * 8];
            pah[1] = *(const uint4*)&Ahi[(size_t)(m0 + ar1) * lda + kt + ac1 * 8];
            pal[0] = *(const uint4*)&Alo[(size_t)(m0 + ar0) * lda + kt + ac0 * 8];
            pal[1] = *(const uint4*)&Alo[(size_t)(m0 + ar1) * lda + kt + ac1 * 8];
            pbh    = *(const uint4*)&Bhi[(size_t)(n0 + br) * ldb + kt + bc * 8];
            pbl    = *(const uint4*)&Blo[(size_t)(n0 + br) * ldb + kt + bc * 8];
        }

        const uint32_t ahs = smem_u32(ah), als = smem_u32(al);
        const uint32_t bhs = smem_u32(bh), bls = smem_u32(bl);
        #pragma unroll
        for (int kk = 0; kk < 2; kk++) {
            const int kb = kk * 32 + gk;
            uint32_t a_hi[2][4], a_lo[2][4], b_hi[2][4], b_lo[2][4];
            #pragma unroll
            for (int mt = 0; mt < 2; mt++) {
                const uint32_t ro = (wm * 32 + mt * 16 + grow) * RS + kb;
                ldm_x4(a_hi[mt], ahs + ro);
                ldm_x4(a_lo[mt], als + ro);
            }
            #pragma unroll
            for (int ng = 0; ng < 2; ng++) {
                const uint32_t ro = (wn * 32 + ng * 16 + grow) * RS + kb;
                ldm_x4(b_hi[ng], bhs + ro);
                ldm_x4(b_lo[ng], bls + ro);
            }
            #pragma unroll
            for (int mt = 0; mt < 2; mt++)
                #pragma unroll
                for (int nt = 0; nt < 4; nt++) {
                    const int ng = nt >> 1, sel = nt & 1;
                    const uint32_t bh0 = b_hi[ng][sel], bh1 = b_hi[ng][sel + 2];
                    const uint32_t bl0 = b_lo[ng][sel], bl1 = b_lo[ng][sel + 2];
                    mma_bf16(acc[mt][nt], a_hi[mt], bh0, bh1);
                    mma_bf16(acc[mt][nt], a_hi[mt], bl0, bl1);
                    mma_bf16(acc[mt][nt], a_lo[mt], bh0, bh1);
                }
        }
        __syncthreads();
    }

    // epilogue
    const int qr = lane >> 2, qc = (lane & 3) * 2;
    #pragma unroll
    for (int mt = 0; mt < 2; mt++) {
        const int r0 = m0 + wm * 32 + mt * 16 + qr;
        const bool z0 = ZMASK ? (rmask[r0] != 0)     : false;
        const bool z1 = ZMASK ? (rmask[r0 + 8] != 0) : false;
        #pragma unroll
        for (int nt = 0; nt < 4; nt++) {
            const int c = n0 + wn * 32 + nt * 8 + qc;
            float b0 = 0.f, b1 = 0.f;
            if (bias) { b0 = bias[(size_t)z * bioz + c]; b1 = bias[(size_t)z * bioz + c + 1]; }
            float2 v0 = make_float2(acc[mt][nt][0] + b0, acc[mt][nt][1] + b1);
            float2 v1 = make_float2(acc[mt][nt][2] + b0, acc[mt][nt][3] + b1);
            if (z0) v0 = make_float2(0.f, 0.f);
            if (z1) v1 = make_float2(0.f, 0.f);
            const size_t o0 = (size_t)z * coz + (size_t)r0 * ldc + c;
            const size_t o1 = o0 + (size_t)8 * ldc;
            if (EMIT & 1) {
                *(float2*)&C[o0] = v0;
                *(float2*)&C[o1] = v1;
            }
            if (EMIT & 2) {
                split2_store(v0.x, v0.y, Chi, Clo, o0);
                split2_store(v1.x, v1.y, Chi, Clo, o1);
            }
        }
    }
}

// ======================= fused attention core (v3) =========================
// logits: warp = K-eighth (16 f4), lane = t, all 8 heads in regs -> tile read
// exactly once; partial reduce via 8KB smem slab. u-phase: tile read once,
// writes U directly as bf16 hi/lo planes (fp32 U eliminated).
__global__ __launch_bounds__(256) void attn_core(
    const float* __restrict__ tgt,
    const float* __restrict__ Q,
    const float* __restrict__ P,
    const void* __restrict__ mask_raw,
    const int* __restrict__ mask_mode,
    const float* __restrict__ ipb,
    bf16* __restrict__ Uhi, bf16* __restrict__ Ulo,
    int* __restrict__ allm)
{
    extern __shared__ float sm[];
    float4* tile4 = (float4*)sm;      // 16384 floats, swizzled
    float*  s_p   = sm + 16384;       // 4096 (reused as reduction buffer)
    float*  s_la  = sm + 20480;       // 2048 partial logits (8 slabs x 256)
    float*  s_a   = sm + 22528;       // 256 softmax weights
    float*  s_c   = sm + 22784;       // 8
    float*  s_m   = sm + 22792;       // 32
    float*  s_am  = sm + 22824;       // 1

    const int i    = blockIdx.x;
    const int tid  = threadIdx.x;
    const int lane = tid & 31, w = tid >> 5;

    const float4* tg = (const float4*)(tgt + (size_t)i * (TT * DM));
    #pragma unroll
    for (int r = 0; r < 16; r++) {
        int gg = tid + 256 * r;
        int t = gg >> 7, k4 = gg & 127;
        tile4[(t << 7) + (k4 ^ (t & 7))] = tg[gg];
    }
    const float4* pg = (const float4*)(P + (size_t)i * (NH * DM));
    float4* sp4 = (float4*)s_p;
    #pragma unroll
    for (int r = 0; r < 4; r++) sp4[tid + 256 * r] = pg[tid + 256 * r];

    {
        const float* qr = Q   + (size_t)i * DM + w * DH;
        const float* br = ipb + DM + w * DH;
        float cs = qr[lane] * br[lane] + qr[lane + 32] * br[lane + 32];
        #pragma unroll
        for (int off = 16; off; off >>= 1)
            cs += __shfl_down_sync(0xffffffffu, cs, off);
        if (lane == 0) s_c[w] = cs;
    }
    if (w == 0) {
        const int mode = *mask_mode;
        unsigned mv;
        if (mode == 0)      mv = ((const unsigned char*)mask_raw)[(size_t)i * TT + lane];
        else if (mode == 1) mv = ((const unsigned*)mask_raw)[(size_t)i * TT + lane] != 0u;
        else                mv = ((const float*)mask_raw)[(size_t)i * TT + lane] != 0.f;
        s_m[lane] = mv ? 1.f : 0.f;
        unsigned bal = __ballot_sync(0xffffffffu, mv != 0);
        if (lane == 0) {
            int am = (bal == 0xffffffffu) ? 1 : 0;
            s_am[0] = (float)am;
            allm[i] = am;
        }
    }
    __syncthreads();

    // logits partials: warp w covers k4 in [w*16, w*16+16), lane = t, 8 heads
    {
        const int kb0 = w << 4;
        const int cx = lane & 7, tb = lane << 7;
        float s[NH] = {};
        #pragma unroll
        for (int j = 0; j < 16; j++) {
            const int k4 = kb0 + j;
            const float4 tv = tile4[tb + (k4 ^ cx)];
            #pragma unroll
            for (int h = 0; h < NH; h++) {
                const float4 pv = ((const float4*)(s_p + h * DM))[k4];
                s[h] += tv.x * pv.x + tv.y * pv.y + tv.z * pv.z + tv.w * pv.w;
            }
        }
        #pragma unroll
        for (int h = 0; h < NH; h++)
            s_la[(w << 8) + (h << 5) + lane] = s[h];
    }
    __syncthreads();

    // reduce partials + softmax (warp w = head w, lane = t)
    {
        const float am = s_am[0];
        float l = s_c[w];
        #pragma unroll
        for (int j = 0; j < 8; j++) l += s_la[(j << 8) + (w << 5) + lane];
        const bool inv = (s_m[lane] != 0.f) && (am == 0.f);
        l = inv ? -1e30f : l * 0.125f;
        float m = l;
        #pragma unroll
        for (int off = 16; off; off >>= 1)
            m = fmaxf(m, __shfl_xor_sync(0xffffffffu, m, off));
        float e = inv ? 0.f : __expf(l - m);
        float s = e;
        #pragma unroll
        for (int off = 16; off; off >>= 1)
            s += __shfl_xor_sync(0xffffffffu, s, off);
        s_a[(w << 5) + lane] = e / s;
    }
    __syncthreads();

    // u[h][k4] = sum_t a[h][t] * tile[t][k4]; thread = (k4, t-half)
    {
        const int k4 = tid & 127, half = tid >> 7;
        float4 acc[NH];
        #pragma unroll
        for (int h = 0; h < NH; h++) acc[h] = make_float4(0.f, 0.f, 0.f, 0.f);
        const int t0 = half << 4;
        #pragma unroll
        for (int j = 0; j < 16; j++) {
            const int t = t0 + j;
            float4 tv = tile4[(t << 7) + (k4 ^ (t & 7))];
            #pragma unroll
            for (int h = 0; h < NH; h++) {
                float a = s_a[(h << 5) + t];
                acc[h].x += a * tv.x; acc[h].y += a * tv.y;
                acc[h].z += a * tv.z; acc[h].w += a * tv.w;
            }
        }
        float4* red = (float4*)s_p;   // dead after logits
        if (half) {
            #pragma unroll
            for (int h = 0; h < NH; h++) red[(h << 7) + k4] = acc[h];
        }
        __syncthreads();
        if (!half) {
            const size_t base = (size_t)i * (NH * DM);
            #pragma unroll
            for (int h = 0; h < NH; h++) {
                float4 rv = red[(h << 7) + k4];
                float4 v = make_float4(acc[h].x + rv.x, acc[h].y + rv.y,
                                       acc[h].z + rv.z, acc[h].w + rv.w);
                uint2 hh, ll; split4(v, hh, ll);
                const size_t o = base + (h << 9) + (k4 << 2);
                *(uint2*)&Uhi[o] = hh;
                *(uint2*)&Ulo[o] = ll;
            }
        }
    }
}

// ======================= launch ============================================
extern "C" void kernel_launch(void* const* d_in, const int* in_sizes, int n_in,
                              void* d_out, int out_size) {
    const float* src  = (const float*)d_in[0];
    const float* tgt  = (const float*)d_in[1];
    const void*  mask = d_in[2];
    const float* ipw  = (const float*)d_in[3];
    const float* ipb  = (const float*)d_in[4];
    const float* opw  = (const float*)d_in[5];
    const float* opb  = (const float*)d_in[6];
    float*       out  = (float*)d_out;

    float *Q, *P; int *AM, *MODE;
    bf16 *SRCh, *SRCl, *Qh, *Ql, *Uh, *Ul, *CTXh, *CTXl;
    bf16 *WQh, *WQl, *WKTh, *WKTl, *WVh, *WVl, *WOh, *WOl;
    cudaGetSymbolAddress((void**)&Q,    g_Q);
    cudaGetSymbolAddress((void**)&P,    g_P);
    cudaGetSymbolAddress((void**)&AM,   g_AM);
    cudaGetSymbolAddress((void**)&MODE, g_MaskMode);
    cudaGetSymbolAddress((void**)&SRCh, g_SRCh); cudaGetSymbolAddress((void**)&SRCl, g_SRCl);
    cudaGetSymbolAddress((void**)&Qh,   g_Qh);   cudaGetSymbolAddress((void**)&Ql,   g_Ql);
    cudaGetSymbolAddress((void**)&Uh,   g_Uh);   cudaGetSymbolAddress((void**)&Ul,   g_Ul);
    cudaGetSymbolAddress((void**)&CTXh, g_CTXh); cudaGetSymbolAddress((void**)&CTXl, g_CTXl);
    cudaGetSymbolAddress((void**)&WQh,  g_WQh);  cudaGetSymbolAddress((void**)&WQl,  g_WQl);
    cudaGetSymbolAddress((void**)&WKTh, g_WKTh); cudaGetSymbolAddress((void**)&WKTl, g_WKTl);
    cudaGetSymbolAddress((void**)&WVh,  g_WVh);  cudaGetSymbolAddress((void**)&WVl,  g_WVl);
    cudaGetSymbolAddress((void**)&WOh,  g_WOh);  cudaGetSymbolAddress((void**)&WOl,  g_WOl);

    const int SMG = 2 * 30720;   // 60 KB double-buffered
    cudaFuncSetAttribute(hmma_gemm<3, false>, cudaFuncAttributeMaxDynamicSharedMemorySize, SMG);
    cudaFuncSetAttribute(hmma_gemm<1, false>, cudaFuncAttributeMaxDynamicSharedMemorySize, SMG);
    cudaFuncSetAttribute(hmma_gemm<2, false>, cudaFuncAttributeMaxDynamicSharedMemorySize, SMG);
    cudaFuncSetAttribute(hmma_gemm<1, true>,  cudaFuncAttributeMaxDynamicSharedMemorySize, SMG);

    // 0) mask dtype + operand splits (one-shot, memory-bound)
    detect_mask_kernel<<<1, 256>>>((const unsigned*)mask, 16384, MODE);
    split_f32<<<1024, 256>>>(src, SRCh, SRCl, NPOS * DM / 4);               // src
    split_f32<<<256, 256>>>(ipw, WQh, WQl, DM * DM / 4);                    // Wq
    transpose_wk_split<<<dim3(16, 2, 8), dim3(32, 8)>>>(ipw, WKTh, WKTl);   // Wk^T
    split_f32<<<256, 256>>>(ipw + 1024 * 512, WVh, WVl, DM * DM / 4);       // Wv
    split_f32<<<256, 256>>>(opw, WOh, WOl, DM * DM / 4);                    // Wo

    // 1) Q = src @ Wq^T + bq  -> fp32 Q + bf16 Qh/Ql
    hmma_gemm<3, false><<<dim3(16, 8, 1), 256, SMG>>>(
        SRCh, SRCl, 512, 0, WQh, WQl, 512, 0,
        Q, Qh, Ql, 512, 0, ipb, 0, 512, nullptr);

    // 2) P[:,h,:] = Q_h @ WkT_h^T  -> fp32 P (consumed by attn SIMT)
    hmma_gemm<1, false><<<dim3(16, 8, 8), 256, SMG>>>(
        Qh, Ql, 512, 64, WKTh, WKTl, 64, 512 * 64,
        P, nullptr, nullptr, 4096, 512, nullptr, 0, 64, nullptr);

    // 3) fused attention: logits -> softmax -> U (bf16 hi/lo direct)
    const int smemA = 22825 * 4;
    cudaFuncSetAttribute(attn_core, cudaFuncAttributeMaxDynamicSharedMemorySize, smemA);
    attn_core<<<2048, 256, smemA>>>(tgt, Q, P, mask, MODE, ipb, Uh, Ul, AM);

    // 4) ctx_h = U_h @ Wv_h^T + bv  -> bf16 CTXh/CTXl only
    hmma_gemm<2, false><<<dim3(16, 1, 8), 256, SMG>>>(
        Uh, Ul, 4096, 512, WVh, WVl, 512, 64 * 512,
        nullptr, CTXh, CTXl, 512, 64, ipb + 1024, 64, 512, nullptr);

    // 5) out = ctx @ Wo^T + bo, zeroing all-masked rows
    hmma_gemm<1, true><<<dim3(16, 8, 1), 256, SMG>>>(
        CTXh, CTXl, 512, 0, WOh, WOl, 512, 0,
        out, nullptr, nullptr, 512, 0, opb, 0, 512, AM);
}

// round 10
// speedup vs baseline: 2.2050x; 1.1068x over previous
#include <cuda_runtime.h>
#include <cuda_bf16.h>
#include <cstdint>

// Problem constants
#define NPOS 2048   // B*S
#define DM   512
#define NH   8
#define DH   64
#define TT   32

typedef __nv_bfloat16 bf16;

// Scratch (device globals)
__device__ float g_Q  [NPOS * DM];
__device__ float g_P  [NPOS * NH * DM];
__device__ int   g_AM [NPOS];
__device__ int   g_MaskMode;
__device__ __align__(16) bf16 g_SRCh[NPOS * DM],      g_SRCl[NPOS * DM];
__device__ __align__(16) bf16 g_Qh  [NPOS * DM],      g_Ql  [NPOS * DM];
__device__ __align__(16) bf16 g_Uh  [NPOS * NH * DM], g_Ul  [NPOS * NH * DM];
__device__ __align__(16) bf16 g_CTXh[NPOS * DM],      g_CTXl[NPOS * DM];
__device__ __align__(16) bf16 g_WQh [DM * DM],        g_WQl [DM * DM];
__device__ __align__(16) bf16 g_WKTh[NH * DM * DH],   g_WKTl[NH * DM * DH];
__device__ __align__(16) bf16 g_WVh [DM * DM],        g_WVl [DM * DM];
__device__ __align__(16) bf16 g_WOh [DM * DM],        g_WOl [DM * DM];

// ======================= helpers ===========================================
__device__ __forceinline__ uint32_t smem_u32(const void* p) {
    uint32_t a;
    asm("{ .reg .u64 t; cvta.to.shared.u64 t, %1; cvt.u32.u64 %0, t; }"
        : "=r"(a) : "l"(p));
    return a;
}
__device__ __forceinline__ void ldm_x4(uint32_t* r, uint32_t addr) {
    asm volatile("ldmatrix.sync.aligned.m8n8.x4.shared.b16 {%0,%1,%2,%3}, [%4];"
                 : "=r"(r[0]), "=r"(r[1]), "=r"(r[2]), "=r"(r[3]) : "r"(addr));
}
__device__ __forceinline__ void mma_bf16(float* d, const uint32_t* a,
                                         uint32_t b0, uint32_t b1) {
    asm volatile(
        "mma.sync.aligned.m16n8k16.row.col.f32.bf16.bf16.f32 "
        "{%0,%1,%2,%3}, {%4,%5,%6,%7}, {%8,%9}, {%0,%1,%2,%3};"
        : "+f"(d[0]), "+f"(d[1]), "+f"(d[2]), "+f"(d[3])
        : "r"(a[0]), "r"(a[1]), "r"(a[2]), "r"(a[3]), "r"(b0), "r"(b1));
}
#define CP_ASYNC16(dst, src) \
    asm volatile("cp.async.cg.shared.global [%0], [%1], 16;" \
                 :: "r"(dst), "l"(src) : "memory")
#define CP_COMMIT() asm volatile("cp.async.commit_group;" ::: "memory")
#define CP_WAIT1()  asm volatile("cp.async.wait_group 1;" ::: "memory")

__device__ __forceinline__ unsigned pack_bf2(bf16 a, bf16 b) {
    __nv_bfloat162 t; t.x = a; t.y = b;
    return *reinterpret_cast<unsigned*>(&t);
}
__device__ __forceinline__ void split4(float4 v, uint2& hi, uint2& lo) {
    bf16 hx = __float2bfloat16(v.x), hy = __float2bfloat16(v.y);
    bf16 hz = __float2bfloat16(v.z), hw = __float2bfloat16(v.w);
    bf16 lx = __float2bfloat16(v.x - __bfloat162float(hx));
    bf16 ly = __float2bfloat16(v.y - __bfloat162float(hy));
    bf16 lz = __float2bfloat16(v.z - __bfloat162float(hz));
    bf16 lw = __float2bfloat16(v.w - __bfloat162float(hw));
    hi = make_uint2(pack_bf2(hx, hy), pack_bf2(hz, hw));
    lo = make_uint2(pack_bf2(lx, ly), pack_bf2(lz, lw));
}
__device__ __forceinline__ void split2_store(float x, float y,
                                             bf16* hi, bf16* lo, size_t off) {
    bf16 hx = __float2bfloat16(x), hy = __float2bfloat16(y);
    bf16 lx = __float2bfloat16(x - __bfloat162float(hx));
    bf16 ly = __float2bfloat16(y - __bfloat162float(hy));
    *(uint32_t*)&hi[off] = pack_bf2(hx, hy);
    *(uint32_t*)&lo[off] = pack_bf2(lx, ly);
}

// ======================= fused prep kernel =================================
// blocks [0,1024): src split; [1024,1280): Wq; [1280,1536): Wv;
// [1536,1792): Wo; [1792,2048): Wk transpose-split; block 2048: mask detect.
__global__ __launch_bounds__(256) void prep_all(
    const float* __restrict__ src, const float* __restrict__ ipw,
    const float* __restrict__ opw, const void* __restrict__ mask,
    bf16* __restrict__ SRCh, bf16* __restrict__ SRCl,
    bf16* __restrict__ WQh,  bf16* __restrict__ WQl,
    bf16* __restrict__ WVh,  bf16* __restrict__ WVl,
    bf16* __restrict__ WOh,  bf16* __restrict__ WOl,
    bf16* __restrict__ WKTh, bf16* __restrict__ WKTl,
    int* __restrict__ mode)
{
    const int b = blockIdx.x, tid = threadIdx.x;
    if (b < 1792) {
        const float* x; bf16 *hi, *lo; int i;
        if (b < 1024)      { x = src;             hi = SRCh; lo = SRCl; i = b * 256 + tid; }
        else if (b < 1280) { x = ipw;             hi = WQh;  lo = WQl;  i = (b - 1024) * 256 + tid; }
        else if (b < 1536) { x = ipw + 1024*512;  hi = WVh;  lo = WVl;  i = (b - 1280) * 256 + tid; }
        else               { x = opw;             hi = WOh;  lo = WOl;  i = (b - 1536) * 256 + tid; }
        float4 v = ((const float4*)x)[i];
        uint2 h, l; split4(v, h, l);
        ((uint2*)hi)[i] = h; ((uint2*)lo)[i] = l;
    } else if (b < 2048) {
        // Wk transpose: wkt[h][n][k] = ipw[512 + h*64 + k][n]
        __shared__ float t[32][33];
        const int r = b - 1792;
        const int h = r >> 5, nb = (r & 15) * 32, kb = ((r >> 4) & 1) * 32;
        const int x = tid & 31, y = tid >> 5;   // 32 x 8
        for (int i = y; i < 32; i += 8)
            t[i][x] = ipw[(size_t)(512 + h * 64 + kb + i) * 512 + nb + x];
        __syncthreads();
        for (int i = y; i < 32; i += 8) {
            float v = t[x][i];
            size_t o = (size_t)h * (512 * 64) + (size_t)(nb + i) * 64 + kb + x;
            bf16 bh = __float2bfloat16(v);
            WKTh[o] = bh;
            WKTl[o] = __float2bfloat16(v - __bfloat162float(bh));
        }
    } else {
        // mask dtype detect over first 16384 words
        __shared__ int flags[2];
        if (tid < 2) flags[tid] = 0;
        __syncthreads();
        const unsigned* w = (const unsigned*)mask;
        for (int j = tid; j < 16384; j += 256) {
            unsigned v = w[j];
            if (v == 0x3F800000u) atomicOr(&flags[0], 1);
            else if (v > 1u)      atomicOr(&flags[1], 1);
        }
        __syncthreads();
        if (tid == 0) *mode = flags[0] ? 2 : (flags[1] ? 0 : 1);
    }
}

// ======================= HMMA GEMM (cp.async 3-stage) ======================
// C[M,N] = A[M,K] @ B[N,K]^T + bias; A,B pre-split bf16 hi/lo planes.
// Split product: hi*hi + hi*lo + lo*hi (fp32 accum). CTA tile 128x64, BK=32,
// 8 warps = 4(M) x 2(N). Smem rows 80B (conflict-free ldmatrix). 3-stage
// cp.async ring, one barrier per stage. EMIT bit0: fp32 C; bit1: bf16 planes.
template <int EMIT, bool ZMASK>
__global__ __launch_bounds__(256, 2) void hmma_gemm(
    const bf16* __restrict__ Ahi, const bf16* __restrict__ Alo, int lda, int aoz,
    const bf16* __restrict__ Bhi, const bf16* __restrict__ Blo, int ldb, int boz,
    float* __restrict__ C, bf16* __restrict__ Chi, bf16* __restrict__ Clo,
    int ldc, int coz,
    const float* __restrict__ bias, int bioz,
    int K, const int* __restrict__ rmask)
{
    constexpr int RS  = 80;
    constexpr int APL = 128 * RS;            // 10240
    constexpr int BPL = 64 * RS;             // 5120
    constexpr int STG = 2 * APL + 2 * BPL;   // 30720 per stage

    extern __shared__ char smem[];
    const uint32_t sbase = smem_u32(smem);

    const int z = blockIdx.z;
    Ahi += (size_t)z * aoz;  Alo += (size_t)z * aoz;
    Bhi += (size_t)z * boz;  Blo += (size_t)z * boz;
    const int m0 = blockIdx.x * 128, n0 = blockIdx.y * 64;

    const int tid = threadIdx.x, lane = tid & 31, wid = tid >> 5;
    const int wm = wid & 3, wn = wid >> 2;

    const int ar0 = tid >> 2,         ac0 = tid & 3;
    const int ar1 = (tid + 256) >> 2;                 // ac1 == ac0
    const int br  = tid >> 2,         bc  = tid & 3;

    const int g = lane >> 3, lr = lane & 7;
    const int grow = (g & 1) * 8 + lr;
    const int gk   = (g >> 1) * 16;

    float acc[2][4][4] = {};
    const int nst = K >> 5;

    // per-stage cp.async issue (6 x 16B per thread)
    auto issue = [&](int s) {
        const int kt = s << 5;
        const uint32_t sb = sbase + (s % 3) * STG;
        CP_ASYNC16(sb + ar0 * RS + ac0 * 16,
                   &Ahi[(size_t)(m0 + ar0) * lda + kt + ac0 * 8]);
        CP_ASYNC16(sb + ar1 * RS + ac0 * 16,
                   &Ahi[(size_t)(m0 + ar1) * lda + kt + ac0 * 8]);
        CP_ASYNC16(sb + APL + ar0 * RS + ac0 * 16,
                   &Alo[(size_t)(m0 + ar0) * lda + kt + ac0 * 8]);
        CP_ASYNC16(sb + APL + ar1 * RS + ac0 * 16,
                   &Alo[(size_t)(m0 + ar1) * lda + kt + ac0 * 8]);
        CP_ASYNC16(sb + 2 * APL + br * RS + bc * 16,
                   &Bhi[(size_t)(n0 + br) * ldb + kt + bc * 8]);
        CP_ASYNC16(sb + 2 * APL + BPL + br * RS + bc * 16,
                   &Blo[(size_t)(n0 + br) * ldb + kt + bc * 8]);
    };

    issue(0); CP_COMMIT();
    if (nst > 1) issue(1);
    CP_COMMIT();

    for (int s = 0; s < nst; s++) {
        CP_WAIT1();            // stage s complete (2 groups in flight max)
        __syncthreads();       // data visible + prior compute on ring slot done
        if (s + 2 < nst) issue(s + 2);
        CP_COMMIT();

        const uint32_t sb = sbase + (s % 3) * STG;
        const uint32_t ahs = sb, als = sb + APL;
        const uint32_t bhs = sb + 2 * APL, bls = bhs + BPL;
        #pragma unroll
        for (int kk = 0; kk < 2; kk++) {
            const int kb = kk * 32 + gk;
            uint32_t a_hi[2][4], a_lo[2][4], b_hi[2][4], b_lo[2][4];
            #pragma unroll
            for (int mt = 0; mt < 2; mt++) {
                const uint32_t ro = (wm * 32 + mt * 16 + grow) * RS + kb;
                ldm_x4(a_hi[mt], ahs + ro);
                ldm_x4(a_lo[mt], als + ro);
            }
            #pragma unroll
            for (int ng = 0; ng < 2; ng++) {
                const uint32_t ro = (wn * 32 + ng * 16 + grow) * RS + kb;
                ldm_x4(b_hi[ng], bhs + ro);
                ldm_x4(b_lo[ng], bls + ro);
            }
            #pragma unroll
            for (int mt = 0; mt < 2; mt++)
                #pragma unroll
                for (int nt = 0; nt < 4; nt++) {
                    const int ng = nt >> 1, sel = nt & 1;
                    const uint32_t bh0 = b_hi[ng][sel], bh1 = b_hi[ng][sel + 2];
                    const uint32_t bl0 = b_lo[ng][sel], bl1 = b_lo[ng][sel + 2];
                    mma_bf16(acc[mt][nt], a_hi[mt], bh0, bh1);
                    mma_bf16(acc[mt][nt], a_hi[mt], bl0, bl1);
                    mma_bf16(acc[mt][nt], a_lo[mt], bh0, bh1);
                }
        }
    }

    // epilogue
    const int qr = lane >> 2, qc = (lane & 3) * 2;
    #pragma unroll
    for (int mt = 0; mt < 2; mt++) {
        const int r0 = m0 + wm * 32 + mt * 16 + qr;
        const bool z0 = ZMASK ? (rmask[r0] != 0)     : false;
        const bool z1 = ZMASK ? (rmask[r0 + 8] != 0) : false;
        #pragma unroll
        for (int nt = 0; nt < 4; nt++) {
            const int c = n0 + wn * 32 + nt * 8 + qc;
            float b0 = 0.f, b1 = 0.f;
            if (bias) { b0 = bias[(size_t)z * bioz + c]; b1 = bias[(size_t)z * bioz + c + 1]; }
            float2 v0 = make_float2(acc[mt][nt][0] + b0, acc[mt][nt][1] + b1);
            float2 v1 = make_float2(acc[mt][nt][2] + b0, acc[mt][nt][3] + b1);
            if (z0) v0 = make_float2(0.f, 0.f);
            if (z1) v1 = make_float2(0.f, 0.f);
            const size_t o0 = (size_t)z * coz + (size_t)r0 * ldc + c;
            const size_t o1 = o0 + (size_t)8 * ldc;
            if (EMIT & 1) { *(float2*)&C[o0] = v0; *(float2*)&C[o1] = v1; }
            if (EMIT & 2) {
                split2_store(v0.x, v0.y, Chi, Clo, o0);
                split2_store(v1.x, v1.y, Chi, Clo, o1);
            }
        }
    }
}

// ======================= fused attention core (unchanged v3) ===============
__global__ __launch_bounds__(256) void attn_core(
    const float* __restrict__ tgt,
    const float* __restrict__ Q,
    const float* __restrict__ P,
    const void* __restrict__ mask_raw,
    const int* __restrict__ mask_mode,
    const float* __restrict__ ipb,
    bf16* __restrict__ Uhi, bf16* __restrict__ Ulo,
    int* __restrict__ allm)
{
    extern __shared__ float sm[];
    float4* tile4 = (float4*)sm;
    float*  s_p   = sm + 16384;
    float*  s_la  = sm + 20480;
    float*  s_a   = sm + 22528;
    float*  s_c   = sm + 22784;
    float*  s_m   = sm + 22792;
    float*  s_am  = sm + 22824;

    const int i    = blockIdx.x;
    const int tid  = threadIdx.x;
    const int lane = tid & 31, w = tid >> 5;

    const float4* tg = (const float4*)(tgt + (size_t)i * (TT * DM));
    #pragma unroll
    for (int r = 0; r < 16; r++) {
        int gg = tid + 256 * r;
        int t = gg >> 7, k4 = gg & 127;
        tile4[(t << 7) + (k4 ^ (t & 7))] = tg[gg];
    }
    const float4* pg = (const float4*)(P + (size_t)i * (NH * DM));
    float4* sp4 = (float4*)s_p;
    #pragma unroll
    for (int r = 0; r < 4; r++) sp4[tid + 256 * r] = pg[tid + 256 * r];

    {
        const float* qr = Q   + (size_t)i * DM + w * DH;
        const float* br = ipb + DM + w * DH;
        float cs = qr[lane] * br[lane] + qr[lane + 32] * br[lane + 32];
        #pragma unroll
        for (int off = 16; off; off >>= 1)
            cs += __shfl_down_sync(0xffffffffu, cs, off);
        if (lane == 0) s_c[w] = cs;
    }
    if (w == 0) {
        const int mode = *mask_mode;
        unsigned mv;
        if (mode == 0)      mv = ((const unsigned char*)mask_raw)[(size_t)i * TT + lane];
        else if (mode == 1) mv = ((const unsigned*)mask_raw)[(size_t)i * TT + lane] != 0u;
        else                mv = ((const float*)mask_raw)[(size_t)i * TT + lane] != 0.f;
        s_m[lane] = mv ? 1.f : 0.f;
        unsigned bal = __ballot_sync(0xffffffffu, mv != 0);
        if (lane == 0) {
            int am = (bal == 0xffffffffu) ? 1 : 0;
            s_am[0] = (float)am;
            allm[i] = am;
        }
    }
    __syncthreads();

    {
        const int kb0 = w << 4;
        const int cx = lane & 7, tb = lane << 7;
        float s[NH] = {};
        #pragma unroll
        for (int j = 0; j < 16; j++) {
            const int k4 = kb0 + j;
            const float4 tv = tile4[tb + (k4 ^ cx)];
            #pragma unroll
            for (int h = 0; h < NH; h++) {
                const float4 pv = ((const float4*)(s_p + h * DM))[k4];
                s[h] += tv.x * pv.x + tv.y * pv.y + tv.z * pv.z + tv.w * pv.w;
            }
        }
        #pragma unroll
        for (int h = 0; h < NH; h++)
            s_la[(w << 8) + (h << 5) + lane] = s[h];
    }
    __syncthreads();

    {
        const float am = s_am[0];
        float l = s_c[w];
        #pragma unroll
        for (int j = 0; j < 8; j++) l += s_la[(j << 8) + (w << 5) + lane];
        const bool inv = (s_m[lane] != 0.f) && (am == 0.f);
        l = inv ? -1e30f : l * 0.125f;
        float m = l;
        #pragma unroll
        for (int off = 16; off; off >>= 1)
            m = fmaxf(m, __shfl_xor_sync(0xffffffffu, m, off));
        float e = inv ? 0.f : __expf(l - m);
        float s = e;
        #pragma unroll
        for (int off = 16; off; off >>= 1)
            s += __shfl_xor_sync(0xffffffffu, s, off);
        s_a[(w << 5) + lane] = e / s;
    }
    __syncthreads();

    {
        const int k4 = tid & 127, half = tid >> 7;
        float4 acc[NH];
        #pragma unroll
        for (int h = 0; h < NH; h++) acc[h] = make_float4(0.f, 0.f, 0.f, 0.f);
        const int t0 = half << 4;
        #pragma unroll
        for (int j = 0; j < 16; j++) {
            const int t = t0 + j;
            float4 tv = tile4[(t << 7) + (k4 ^ (t & 7))];
            #pragma unroll
            for (int h = 0; h < NH; h++) {
                float a = s_a[(h << 5) + t];
                acc[h].x += a * tv.x; acc[h].y += a * tv.y;
                acc[h].z += a * tv.z; acc[h].w += a * tv.w;
            }
        }
        float4* red = (float4*)s_p;
        if (half) {
            #pragma unroll
            for (int h = 0; h < NH; h++) red[(h << 7) + k4] = acc[h];
        }
        __syncthreads();
        if (!half) {
            const size_t base = (size_t)i * (NH * DM);
            #pragma unroll
            for (int h = 0; h < NH; h++) {
                float4 rv = red[(h << 7) + k4];
                float4 v = make_float4(acc[h].x + rv.x, acc[h].y + rv.y,
                                       acc[h].z + rv.z, acc[h].w + rv.w);
                uint2 hh, ll; split4(v, hh, ll);
                const size_t o = base + (h << 9) + (k4 << 2);
                *(uint2*)&Uhi[o] = hh;
                *(uint2*)&Ulo[o] = ll;
            }
        }
    }
}

// ======================= launch ============================================
extern "C" void kernel_launch(void* const* d_in, const int* in_sizes, int n_in,
                              void* d_out, int out_size) {
    const float* src  = (const float*)d_in[0];
    const float* tgt  = (const float*)d_in[1];
    const void*  mask = d_in[2];
    const float* ipw  = (const float*)d_in[3];
    const float* ipb  = (const float*)d_in[4];
    const float* opw  = (const float*)d_in[5];
    const float* opb  = (const float*)d_in[6];
    float*       out  = (float*)d_out;

    float *Q, *P; int *AM, *MODE;
    bf16 *SRCh, *SRCl, *Qh, *Ql, *Uh, *Ul, *CTXh, *CTXl;
    bf16 *WQh, *WQl, *WKTh, *WKTl, *WVh, *WVl, *WOh, *WOl;
    cudaGetSymbolAddress((void**)&Q,    g_Q);
    cudaGetSymbolAddress((void**)&P,    g_P);
    cudaGetSymbolAddress((void**)&AM,   g_AM);
    cudaGetSymbolAddress((void**)&MODE, g_MaskMode);
    cudaGetSymbolAddress((void**)&SRCh, g_SRCh); cudaGetSymbolAddress((void**)&SRCl, g_SRCl);
    cudaGetSymbolAddress((void**)&Qh,   g_Qh);   cudaGetSymbolAddress((void**)&Ql,   g_Ql);
    cudaGetSymbolAddress((void**)&Uh,   g_Uh);   cudaGetSymbolAddress((void**)&Ul,   g_Ul);
    cudaGetSymbolAddress((void**)&CTXh, g_CTXh); cudaGetSymbolAddress((void**)&CTXl, g_CTXl);
    cudaGetSymbolAddress((void**)&WQh,  g_WQh);  cudaGetSymbolAddress((void**)&WQl,  g_WQl);
    cudaGetSymbolAddress((void**)&WKTh, g_WKTh); cudaGetSymbolAddress((void**)&WKTl, g_WKTl);
    cudaGetSymbolAddress((void**)&WVh,  g_WVh);  cudaGetSymbolAddress((void**)&WVl,  g_WVl);
    cudaGetSymbolAddress((void**)&WOh,  g_WOh);  cudaGetSymbolAddress((void**)&WOl,  g_WOl);

    const int SMG = 3 * 30720;   // 90 KB, 3-stage ring
    cudaFuncSetAttribute(hmma_gemm<3, false>, cudaFuncAttributeMaxDynamicSharedMemorySize, SMG);
    cudaFuncSetAttribute(hmma_gemm<1, false>, cudaFuncAttributeMaxDynamicSharedMemorySize, SMG);
    cudaFuncSetAttribute(hmma_gemm<2, false>, cudaFuncAttributeMaxDynamicSharedMemorySize, SMG);
    cudaFuncSetAttribute(hmma_gemm<1, true>,  cudaFuncAttributeMaxDynamicSharedMemorySize, SMG);

    // 0) all prep in one launch
    prep_all<<<2049, 256>>>(src, ipw, opw, mask,
                            SRCh, SRCl, WQh, WQl, WVh, WVl, WOh, WOl,
                            WKTh, WKTl, MODE);

    // 1) Q = src @ Wq^T + bq  -> fp32 Q + bf16 Qh/Ql
    hmma_gemm<3, false><<<dim3(16, 8, 1), 256, SMG>>>(
        SRCh, SRCl, 512, 0, WQh, WQl, 512, 0,
        Q, Qh, Ql, 512, 0, ipb, 0, 512, nullptr);

    // 2) P[:,h,:] = Q_h @ WkT_h^T  -> fp32 P
    hmma_gemm<1, false><<<dim3(16, 8, 8), 256, SMG>>>(
        Qh, Ql, 512, 64, WKTh, WKTl, 64, 512 * 64,
        P, nullptr, nullptr, 4096, 512, nullptr, 0, 64, nullptr);

    // 3) fused attention: logits -> softmax -> U (bf16 hi/lo direct)
    const int smemA = 22825 * 4;
    cudaFuncSetAttribute(attn_core, cudaFuncAttributeMaxDynamicSharedMemorySize, smemA);
    attn_core<<<2048, 256, smemA>>>(tgt, Q, P, mask, MODE, ipb, Uh, Ul, AM);

    // 4) ctx_h = U_h @ Wv_h^T + bv  -> bf16 CTXh/CTXl only
    hmma_gemm<2, false><<<dim3(16, 1, 8), 256, SMG>>>(
        Uh, Ul, 4096, 512, WVh, WVl, 512, 64 * 512,
        nullptr, CTXh, CTXl, 512, 64, ipb + 1024, 64, 512, nullptr);

    // 5) out = ctx @ Wo^T + bo, zeroing all-masked rows
    hmma_gemm<1, true><<<dim3(16, 8, 1), 256, SMG>>>(
        CTXh, CTXl, 512, 0, WOh, WOl, 512, 0,
        out, nullptr, nullptr, 512, 0, opb, 0, 512, AM);
}